// round 3
// baseline (speedup 1.0000x reference)
#include <cuda_runtime.h>
#include <cuda_bf16.h>
#include <mma.h>
#include <cstdint>

using namespace nvcuda;

#define DEVINL __device__ __forceinline__

static constexpr int B_ = 8;
static constexpr int L_ = 2048;
static constexpr int D_ = 128;
static constexpr int TILE = 128;

// Padded strides (elements)
static constexpr int LDB = 136;   // bf16 tiles: 272B rows, odd multiple of 16B
static constexpr int LDC = 132;   // f32 C / mask tiles: 528B rows

static constexpr int TILE_BYTES = 128 * LDB * 2;       // 34816

// ---- scores kernel smem layout ----
static constexpr int S_MASK = 0;                       // 128*132*4 = 67584
static constexpr int S_QH = 67584;
static constexpr int S_QL = S_QH + TILE_BYTES;         // 102400
static constexpr int S_KH = S_QL + TILE_BYTES;         // 137216
static constexpr int S_KL = S_KH + TILE_BYTES;         // 172032
static constexpr int S_SMEM = S_KL + TILE_BYTES;       // 206848

// ---- proj kernel smem layout ----
static constexpr int P_BIAS = 0;                       // 512B
static constexpr int P_XH = 1024;
static constexpr int P_XL = P_XH + TILE_BYTES;
static constexpr int P_WH = P_XL + TILE_BYTES;
static constexpr int P_WL = P_WH + TILE_BYTES;
static constexpr int P_SMEM = P_WL + TILE_BYTES;       // 140288
static constexpr int P_C = P_XH;                       // overlay (67584 <= 69632)

// ---------------------------------------------------------------------------
// Scratch (device globals; allocation-free per harness rules)
// p: qm=0, km=1, qs=2, ks=3
// ---------------------------------------------------------------------------
__device__ __align__(16) __nv_bfloat16 g_ph[4][(size_t)B_ * L_ * D_];
__device__ __align__(16) __nv_bfloat16 g_pl[4][(size_t)B_ * L_ * D_];
__device__ __align__(16) __nv_bfloat16 g_wh[4][D_ * D_];
__device__ __align__(16) __nv_bfloat16 g_wl[4][D_ * D_];

// ---------------------------------------------------------------------------
DEVINL uint32_t smem_u32(const void* p) {
    uint32_t a;
    asm("{ .reg .u64 t; cvta.to.shared.u64 t, %1; cvt.u32.u64 %0, t; }" : "=r"(a) : "l"(p));
    return a;
}
DEVINL void cp_async16(uint32_t dst, const void* src) {
    asm volatile("cp.async.cg.shared.global [%0], [%1], 16;" :: "r"(dst), "l"(src) : "memory");
}
DEVINL void cp_async_wait_all() {
    asm volatile("cp.async.wait_all;" ::: "memory");
}

DEVINL uint32_t pack2(__nv_bfloat16 a, __nv_bfloat16 b) {
    return (uint32_t)__bfloat16_as_ushort(a) | ((uint32_t)__bfloat16_as_ushort(b) << 16);
}
DEVINL void split2(float a, float b, uint32_t& h, uint32_t& l) {
    __nv_bfloat16 ha = __float2bfloat16_rn(a);
    __nv_bfloat16 hb = __float2bfloat16_rn(b);
    __nv_bfloat16 la = __float2bfloat16_rn(a - __bfloat162float(ha));
    __nv_bfloat16 lb = __float2bfloat16_rn(b - __bfloat162float(hb));
    h = pack2(ha, hb);
    l = pack2(la, lb);
}

// accurate tanh: 1 EX2 + 1 RCP-based fast div (2 MUFU lane-ops)
DEVINL float tanh_fast(float x) {
    x = fminf(fmaxf(x, -15.0f), 15.0f);
    float e = __expf(2.0f * x);
    return __fdividef(e - 1.0f, e + 1.0f);
}

// Load a 128x128 bf16 tile (row-major 256B rows) into padded smem (272B rows).
DEVINL void load_tile_cp(uint32_t dst, const __nv_bfloat16* src, int tid) {
    const char* s = reinterpret_cast<const char*>(src);
#pragma unroll
    for (int i = 0; i < 8; i++) {
        int idx = i * 256 + tid;
        int r = idx >> 4, c = idx & 15;
        cp_async16(dst + r * 272 + c * 16, s + r * 256 + c * 16);
    }
}

typedef wmma::fragment<wmma::matrix_a, 16, 16, 16, __nv_bfloat16, wmma::row_major> FragA;
typedef wmma::fragment<wmma::matrix_b, 16, 16, 16, __nv_bfloat16, wmma::col_major> FragBc;
typedef wmma::fragment<wmma::matrix_b, 16, 16, 16, __nv_bfloat16, wmma::row_major> FragBr;
typedef wmma::fragment<wmma::accumulator, 16, 16, 16, float> FragC;

// ---------------------------------------------------------------------------
// Kernel 0: hi/lo split of the four [D,D] weight matrices (kept [in][out]).
// ---------------------------------------------------------------------------
__global__ void wprep_kernel(const float* __restrict__ wqm, const float* __restrict__ wkm,
                             const float* __restrict__ wqs, const float* __restrict__ wks) {
    int p = blockIdx.y;
    const float* W = (p == 0) ? wqm : (p == 1) ? wkm : (p == 2) ? wqs : wks;
    int i = blockIdx.x * blockDim.x + threadIdx.x;
    float w = W[i];
    __nv_bfloat16 h = __float2bfloat16_rn(w);
    g_wh[p][i] = h;
    g_wl[p][i] = __float2bfloat16_rn(w - __bfloat162float(h));
}

// ---------------------------------------------------------------------------
// Kernel 1: projections Y = X @ W + b, output split hi/lo bf16 to scratch.
// 256 threads, 8 warps each computing 32x64 of the 128x128 tile.
// ---------------------------------------------------------------------------
__global__ __launch_bounds__(256, 1)
void proj_kernel(const float* __restrict__ query, const float* __restrict__ key,
                 const float* __restrict__ bqm, const float* __restrict__ bkm,
                 const float* __restrict__ bqs, const float* __restrict__ bks) {
    extern __shared__ __align__(16) char smem[];
    const int tid = threadIdx.x, wid = tid >> 5;
    const int p = blockIdx.y;
    const int m0 = blockIdx.x * TILE;
    const uint32_t sbase = smem_u32(smem);

    const float* src  = (p & 1) ? key : query;
    const float* bias = (p == 0) ? bqm : (p == 1) ? bkm : (p == 2) ? bqs : bks;

    float* sbias = reinterpret_cast<float*>(smem + P_BIAS);
    if (tid < 128) sbias[tid] = bias[tid];

    // W tiles via cp.async
    load_tile_cp(sbase + P_WH, g_wh[p], tid);
    load_tile_cp(sbase + P_WL, g_wl[p], tid);

    // X tile: f32 load -> hi/lo split -> padded smem
#pragma unroll
    for (int i = 0; i < 8; i++) {
        int idx = i * 256 + tid;
        int r = idx >> 4, c = idx & 15;
        const float* sp = src + (size_t)(m0 + r) * D_ + c * 8;
        float4 v0 = *reinterpret_cast<const float4*>(sp);
        float4 v1 = *reinterpret_cast<const float4*>(sp + 4);
        uint4 H, Lo;
        split2(v0.x, v0.y, H.x, Lo.x);
        split2(v0.z, v0.w, H.y, Lo.y);
        split2(v1.x, v1.y, H.z, Lo.z);
        split2(v1.z, v1.w, H.w, Lo.w);
        *reinterpret_cast<uint4*>(smem + P_XH + r * 272 + c * 16) = H;
        *reinterpret_cast<uint4*>(smem + P_XL + r * 272 + c * 16) = Lo;
    }

    cp_async_wait_all();
    __syncthreads();

    const int wm = wid & 3, wn = wid >> 2;   // 4 x 2 warp grid -> 32 x 64 each
    const __nv_bfloat16* sXh = reinterpret_cast<const __nv_bfloat16*>(smem + P_XH);
    const __nv_bfloat16* sXl = reinterpret_cast<const __nv_bfloat16*>(smem + P_XL);
    const __nv_bfloat16* sWh = reinterpret_cast<const __nv_bfloat16*>(smem + P_WH);
    const __nv_bfloat16* sWl = reinterpret_cast<const __nv_bfloat16*>(smem + P_WL);

    FragC acc[2][4];
#pragma unroll
    for (int i = 0; i < 2; i++)
#pragma unroll
        for (int j = 0; j < 4; j++) wmma::fill_fragment(acc[i][j], 0.0f);

#pragma unroll
    for (int pass = 0; pass < 3; pass++) {
        const __nv_bfloat16* A = (pass == 1) ? sXl : sXh;
        const __nv_bfloat16* Bm = (pass == 2) ? sWl : sWh;
#pragma unroll
        for (int k = 0; k < 8; k++) {
            FragA a[2];
            wmma::load_matrix_sync(a[0], A + (wm * 32 + 0) * LDB + k * 16, LDB);
            wmma::load_matrix_sync(a[1], A + (wm * 32 + 16) * LDB + k * 16, LDB);
#pragma unroll
            for (int j = 0; j < 4; j++) {
                FragBr b;  // W[k][n] row-major
                wmma::load_matrix_sync(b, Bm + (k * 16) * LDB + (wn * 64 + j * 16), LDB);
                wmma::mma_sync(acc[0][j], a[0], b, acc[0][j]);
                wmma::mma_sync(acc[1][j], a[1], b, acc[1][j]);
            }
        }
    }
    __syncthreads();

    // C -> smem overlay
    float* Cs = reinterpret_cast<float*>(smem + P_C);
#pragma unroll
    for (int i = 0; i < 2; i++)
#pragma unroll
        for (int j = 0; j < 4; j++)
            wmma::store_matrix_sync(Cs + (wm * 32 + i * 16) * LDC + (wn * 64 + j * 16),
                                    acc[i][j], LDC, wmma::mem_row_major);
    __syncthreads();

    // epilogue: + bias, hi/lo split, store scratch
#pragma unroll
    for (int i = 0; i < 16; i++) {
        int u = i * 256 + tid;
        int r = u >> 5, c4 = (u & 31) << 2;
        float4 v = *reinterpret_cast<const float4*>(Cs + r * LDC + c4);
        v.x += sbias[c4 + 0];
        v.y += sbias[c4 + 1];
        v.z += sbias[c4 + 2];
        v.w += sbias[c4 + 3];
        uint32_t h01, l01, h23, l23;
        split2(v.x, v.y, h01, l01);
        split2(v.z, v.w, h23, l23);
        size_t o = (size_t)(m0 + r) * D_ + c4;
        *reinterpret_cast<uint2*>(g_ph[p] + o) = make_uint2(h01, h23);
        *reinterpret_cast<uint2*>(g_pl[p] + o) = make_uint2(l01, l23);
    }
}

// ---------------------------------------------------------------------------
// Kernel 2: scores. CTA = one 128x128 tile of S for one batch; two phases
// (mean p={0,1}, std p={2,3}) reusing SMEM. Mask cached once as float smem,
// consumed as accumulator-layout fragments -> full register epilogue.
// ---------------------------------------------------------------------------
__global__ __launch_bounds__(256, 1)
void scores_kernel(const int* __restrict__ mask, float* __restrict__ out) {
    extern __shared__ __align__(16) char smem[];
    const int tid = threadIdx.x, wid = tid >> 5;
    const int nb0 = blockIdx.x * TILE;
    const int mb0 = blockIdx.y * TILE;
    const int b = blockIdx.z;
    const uint32_t sbase = smem_u32(smem);

    // mask -> float smem (once; reused by both phases)
    float* Ms = reinterpret_cast<float*>(smem + S_MASK);
#pragma unroll
    for (int i = 0; i < 16; i++) {
        int u = i * 256 + tid;
        int r = u >> 5, c4 = (u & 31) << 2;
        int4 mm = *reinterpret_cast<const int4*>(
            mask + ((size_t)b * L_ + mb0 + r) * L_ + nb0 + c4);
        float4 f;
        f.x = mm.x ? 1.0f : 0.0f;
        f.y = mm.y ? 1.0f : 0.0f;
        f.z = mm.z ? 1.0f : 0.0f;
        f.w = mm.w ? 1.0f : 0.0f;
        *reinterpret_cast<float4*>(Ms + r * LDC + c4) = f;
    }

    const int wm = wid & 3, wn = wid >> 2;
    const float inv_sqrt_d = 0.08838834764831845f;

    const __nv_bfloat16* sQh = reinterpret_cast<const __nv_bfloat16*>(smem + S_QH);
    const __nv_bfloat16* sQl = reinterpret_cast<const __nv_bfloat16*>(smem + S_QL);
    const __nv_bfloat16* sKh = reinterpret_cast<const __nv_bfloat16*>(smem + S_KH);
    const __nv_bfloat16* sKl = reinterpret_cast<const __nv_bfloat16*>(smem + S_KL);

    for (int phase = 0; phase < 2; phase++) {
        const size_t qoff = ((size_t)b * L_ + mb0) * D_;
        const size_t koff = ((size_t)b * L_ + nb0) * D_;
        load_tile_cp(sbase + S_QH, g_ph[2 * phase + 0] + qoff, tid);
        load_tile_cp(sbase + S_QL, g_pl[2 * phase + 0] + qoff, tid);
        load_tile_cp(sbase + S_KH, g_ph[2 * phase + 1] + koff, tid);
        load_tile_cp(sbase + S_KL, g_pl[2 * phase + 1] + koff, tid);
        cp_async_wait_all();
        __syncthreads();

        FragC acc[2][4];
#pragma unroll
        for (int i = 0; i < 2; i++)
#pragma unroll
            for (int j = 0; j < 4; j++) wmma::fill_fragment(acc[i][j], 0.0f);

#pragma unroll
        for (int pass = 0; pass < 3; pass++) {
            const __nv_bfloat16* A = (pass == 1) ? sQl : sQh;
            const __nv_bfloat16* Bm = (pass == 2) ? sKl : sKh;
#pragma unroll
            for (int k = 0; k < 8; k++) {
                FragA a[2];
                wmma::load_matrix_sync(a[0], A + (wm * 32 + 0) * LDB + k * 16, LDB);
                wmma::load_matrix_sync(a[1], A + (wm * 32 + 16) * LDB + k * 16, LDB);
#pragma unroll
                for (int j = 0; j < 4; j++) {
                    // K tile row-major [n][k] == col-major (k,n), ld = LDB
                    FragBc bfr;
                    wmma::load_matrix_sync(bfr, Bm + (wn * 64 + j * 16) * LDB + k * 16, LDB);
                    wmma::mma_sync(acc[0][j], a[0], bfr, acc[0][j]);
                    wmma::mma_sync(acc[1][j], a[1], bfr, acc[1][j]);
                }
            }
        }

        // register epilogue: scale -> tanh -> mask select -> store to global
        float* obase = out + (size_t)phase * B_ * L_ * L_ + (size_t)b * L_ * L_;
#pragma unroll
        for (int i = 0; i < 2; i++) {
#pragma unroll
            for (int j = 0; j < 4; j++) {
                int r0 = wm * 32 + i * 16, c0 = wn * 64 + j * 16;
                FragC mf;
                wmma::load_matrix_sync(mf, Ms + r0 * LDC + c0, LDC, wmma::mem_row_major);
#pragma unroll
                for (int e = 0; e < mf.num_elements; e++) {
                    float t = tanh_fast(acc[i][j].x[e] * inv_sqrt_d);
                    bool m = (mf.x[e] != 0.0f);
                    acc[i][j].x[e] = (phase == 0)
                        ? (m ? fmaf(0.5f, t, 0.5f) : 0.0f)
                        : (m ? fmaf(4.0f, t, -6.0f) : -10.0f);
                }
                wmma::store_matrix_sync(obase + (size_t)(mb0 + r0) * L_ + (nb0 + c0),
                                        acc[i][j], L_, wmma::mem_row_major);
            }
        }
        __syncthreads();  // tiles reusable for next phase
    }
}

// ---------------------------------------------------------------------------
extern "C" void kernel_launch(void* const* d_in, const int* in_sizes, int n_in,
                              void* d_out, int out_size) {
    const float* query = (const float*)d_in[0];
    const float* key   = (const float*)d_in[1];
    const int*   mask  = (const int*)d_in[2];
    const float* wqm = (const float*)d_in[3];
    const float* bqm = (const float*)d_in[4];
    const float* wkm = (const float*)d_in[5];
    const float* bkm = (const float*)d_in[6];
    const float* wqs = (const float*)d_in[7];
    const float* bqs = (const float*)d_in[8];
    const float* wks = (const float*)d_in[9];
    const float* bks = (const float*)d_in[10];
    float* out = (float*)d_out;

    cudaFuncSetAttribute(proj_kernel, cudaFuncAttributeMaxDynamicSharedMemorySize, P_SMEM);
    cudaFuncSetAttribute(scores_kernel, cudaFuncAttributeMaxDynamicSharedMemorySize, S_SMEM);

    wprep_kernel<<<dim3(64, 4), 256>>>(wqm, wkm, wqs, wks);
    proj_kernel<<<dim3((B_ * L_) / TILE, 4), 256, P_SMEM>>>(query, key, bqm, bkm, bqs, bks);
    scores_kernel<<<dim3(L_ / TILE, L_ / TILE, B_), 256, S_SMEM>>>(mask, out);
}

// round 4
// speedup vs baseline: 1.0167x; 1.0167x over previous
#include <cuda_runtime.h>
#include <cuda_bf16.h>
#include <mma.h>
#include <cstdint>

using namespace nvcuda;

#define DEVINL __device__ __forceinline__

static constexpr int B_ = 8;
static constexpr int L_ = 2048;
static constexpr int D_ = 128;
static constexpr int TILE = 128;

// Padded strides (elements)
static constexpr int LDB = 136;   // bf16 tiles: 272B rows, odd multiple of 16B
static constexpr int LDC = 132;   // f32 C / mask tiles: 528B rows

static constexpr int TILE_BYTES = 128 * LDB * 2;       // 34816

// ---- scores kernel smem layout ----
static constexpr int S_MASK = 0;                       // 128*132*4 = 67584
static constexpr int S_QH = 67584;
static constexpr int S_QL = S_QH + TILE_BYTES;         // 102400
static constexpr int S_KH = S_QL + TILE_BYTES;         // 137216
static constexpr int S_KL = S_KH + TILE_BYTES;         // 172032
static constexpr int S_SMEM = S_KL + TILE_BYTES;       // 206848

// ---- proj kernel smem layout ----
static constexpr int P_BIAS = 0;                       // 512B
static constexpr int P_XH = 1024;
static constexpr int P_XL = P_XH + TILE_BYTES;
static constexpr int P_WH = P_XL + TILE_BYTES;
static constexpr int P_WL = P_WH + TILE_BYTES;
static constexpr int P_SMEM = P_WL + TILE_BYTES;       // 140288
static constexpr int P_C = P_XH;                       // overlay (67584 <= 69632)

// ---------------------------------------------------------------------------
// Scratch (device globals; allocation-free per harness rules)
// p: qm=0, km=1, qs=2, ks=3
// ---------------------------------------------------------------------------
__device__ __align__(16) __nv_bfloat16 g_ph[4][(size_t)B_ * L_ * D_];
__device__ __align__(16) __nv_bfloat16 g_pl[4][(size_t)B_ * L_ * D_];
__device__ __align__(16) __nv_bfloat16 g_wh[4][D_ * D_];
__device__ __align__(16) __nv_bfloat16 g_wl[4][D_ * D_];

// ---------------------------------------------------------------------------
DEVINL uint32_t smem_u32(const void* p) {
    uint32_t a;
    asm("{ .reg .u64 t; cvta.to.shared.u64 t, %1; cvt.u32.u64 %0, t; }" : "=r"(a) : "l"(p));
    return a;
}
DEVINL void cp_async16(uint32_t dst, const void* src) {
    asm volatile("cp.async.cg.shared.global [%0], [%1], 16;" :: "r"(dst), "l"(src) : "memory");
}
DEVINL void cp_async_wait_all() {
    asm volatile("cp.async.wait_all;" ::: "memory");
}

DEVINL uint32_t pack2(__nv_bfloat16 a, __nv_bfloat16 b) {
    return (uint32_t)__bfloat16_as_ushort(a) | ((uint32_t)__bfloat16_as_ushort(b) << 16);
}
DEVINL void split2(float a, float b, uint32_t& h, uint32_t& l) {
    __nv_bfloat16 ha = __float2bfloat16_rn(a);
    __nv_bfloat16 hb = __float2bfloat16_rn(b);
    __nv_bfloat16 la = __float2bfloat16_rn(a - __bfloat162float(ha));
    __nv_bfloat16 lb = __float2bfloat16_rn(b - __bfloat162float(hb));
    h = pack2(ha, hb);
    l = pack2(la, lb);
}

// accurate tanh: 1 EX2 + 1 RCP-based fast div (2 MUFU lane-ops)
DEVINL float tanh_fast(float x) {
    x = fminf(fmaxf(x, -15.0f), 15.0f);
    float e = __expf(2.0f * x);
    return __fdividef(e - 1.0f, e + 1.0f);
}

// Load a 128x128 bf16 tile (row-major 256B rows) into padded smem (272B rows).
DEVINL void load_tile_cp(uint32_t dst, const __nv_bfloat16* src, int tid) {
    const char* s = reinterpret_cast<const char*>(src);
#pragma unroll
    for (int i = 0; i < 8; i++) {
        int idx = i * 256 + tid;
        int r = idx >> 4, c = idx & 15;
        cp_async16(dst + r * 272 + c * 16, s + r * 256 + c * 16);
    }
}

typedef wmma::fragment<wmma::matrix_a, 16, 16, 16, __nv_bfloat16, wmma::row_major> FragA;
typedef wmma::fragment<wmma::matrix_b, 16, 16, 16, __nv_bfloat16, wmma::col_major> FragBc;
typedef wmma::fragment<wmma::matrix_b, 16, 16, 16, __nv_bfloat16, wmma::row_major> FragBr;
typedef wmma::fragment<wmma::accumulator, 16, 16, 16, float> FragC;

// ---------------------------------------------------------------------------
// Kernel 0: hi/lo split of the four [D,D] weight matrices (kept [in][out]).
// ---------------------------------------------------------------------------
__global__ void wprep_kernel(const float* __restrict__ wqm, const float* __restrict__ wkm,
                             const float* __restrict__ wqs, const float* __restrict__ wks) {
    int p = blockIdx.y;
    const float* W = (p == 0) ? wqm : (p == 1) ? wkm : (p == 2) ? wqs : wks;
    int i = blockIdx.x * blockDim.x + threadIdx.x;
    float w = W[i];
    __nv_bfloat16 h = __float2bfloat16_rn(w);
    g_wh[p][i] = h;
    g_wl[p][i] = __float2bfloat16_rn(w - __bfloat162float(h));
}

// ---------------------------------------------------------------------------
// Kernel 1: projections Y = X @ W + b, output split hi/lo bf16 to scratch.
// 256 threads, 8 warps each computing 32x64 of the 128x128 tile.
// ---------------------------------------------------------------------------
__global__ __launch_bounds__(256, 1)
void proj_kernel(const float* __restrict__ query, const float* __restrict__ key,
                 const float* __restrict__ bqm, const float* __restrict__ bkm,
                 const float* __restrict__ bqs, const float* __restrict__ bks) {
    extern __shared__ __align__(16) char smem[];
    const int tid = threadIdx.x, wid = tid >> 5;
    const int p = blockIdx.y;
    const int m0 = blockIdx.x * TILE;
    const uint32_t sbase = smem_u32(smem);

    const float* src  = (p & 1) ? key : query;
    const float* bias = (p == 0) ? bqm : (p == 1) ? bkm : (p == 2) ? bqs : bks;

    float* sbias = reinterpret_cast<float*>(smem + P_BIAS);
    if (tid < 128) sbias[tid] = bias[tid];

    // W tiles via cp.async
    load_tile_cp(sbase + P_WH, g_wh[p], tid);
    load_tile_cp(sbase + P_WL, g_wl[p], tid);

    // X tile: f32 load -> hi/lo split -> padded smem
#pragma unroll
    for (int i = 0; i < 8; i++) {
        int idx = i * 256 + tid;
        int r = idx >> 4, c = idx & 15;
        const float* sp = src + (size_t)(m0 + r) * D_ + c * 8;
        float4 v0 = *reinterpret_cast<const float4*>(sp);
        float4 v1 = *reinterpret_cast<const float4*>(sp + 4);
        uint4 H, Lo;
        split2(v0.x, v0.y, H.x, Lo.x);
        split2(v0.z, v0.w, H.y, Lo.y);
        split2(v1.x, v1.y, H.z, Lo.z);
        split2(v1.z, v1.w, H.w, Lo.w);
        *reinterpret_cast<uint4*>(smem + P_XH + r * 272 + c * 16) = H;
        *reinterpret_cast<uint4*>(smem + P_XL + r * 272 + c * 16) = Lo;
    }

    cp_async_wait_all();
    __syncthreads();

    const int wm = wid & 3, wn = wid >> 2;   // 4 x 2 warp grid -> 32 x 64 each
    const __nv_bfloat16* sXh = reinterpret_cast<const __nv_bfloat16*>(smem + P_XH);
    const __nv_bfloat16* sXl = reinterpret_cast<const __nv_bfloat16*>(smem + P_XL);
    const __nv_bfloat16* sWh = reinterpret_cast<const __nv_bfloat16*>(smem + P_WH);
    const __nv_bfloat16* sWl = reinterpret_cast<const __nv_bfloat16*>(smem + P_WL);

    FragC acc[2][4];
#pragma unroll
    for (int i = 0; i < 2; i++)
#pragma unroll
        for (int j = 0; j < 4; j++) wmma::fill_fragment(acc[i][j], 0.0f);

#pragma unroll
    for (int pass = 0; pass < 3; pass++) {
        const __nv_bfloat16* A = (pass == 1) ? sXl : sXh;
        const __nv_bfloat16* Bm = (pass == 2) ? sWl : sWh;
#pragma unroll
        for (int k = 0; k < 8; k++) {
            FragA a[2];
            wmma::load_matrix_sync(a[0], A + (wm * 32 + 0) * LDB + k * 16, LDB);
            wmma::load_matrix_sync(a[1], A + (wm * 32 + 16) * LDB + k * 16, LDB);
#pragma unroll
            for (int j = 0; j < 4; j++) {
                FragBr b;  // W[k][n] row-major
                wmma::load_matrix_sync(b, Bm + (k * 16) * LDB + (wn * 64 + j * 16), LDB);
                wmma::mma_sync(acc[0][j], a[0], b, acc[0][j]);
                wmma::mma_sync(acc[1][j], a[1], b, acc[1][j]);
            }
        }
    }
    __syncthreads();

    // C -> smem overlay
    float* Cs = reinterpret_cast<float*>(smem + P_C);
#pragma unroll
    for (int i = 0; i < 2; i++)
#pragma unroll
        for (int j = 0; j < 4; j++)
            wmma::store_matrix_sync(Cs + (wm * 32 + i * 16) * LDC + (wn * 64 + j * 16),
                                    acc[i][j], LDC, wmma::mem_row_major);
    __syncthreads();

    // epilogue: + bias, hi/lo split, store scratch
#pragma unroll
    for (int i = 0; i < 16; i++) {
        int u = i * 256 + tid;
        int r = u >> 5, c4 = (u & 31) << 2;
        float4 v = *reinterpret_cast<const float4*>(Cs + r * LDC + c4);
        v.x += sbias[c4 + 0];
        v.y += sbias[c4 + 1];
        v.z += sbias[c4 + 2];
        v.w += sbias[c4 + 3];
        uint32_t h01, l01, h23, l23;
        split2(v.x, v.y, h01, l01);
        split2(v.z, v.w, h23, l23);
        size_t o = (size_t)(m0 + r) * D_ + c4;
        *reinterpret_cast<uint2*>(g_ph[p] + o) = make_uint2(h01, h23);
        *reinterpret_cast<uint2*>(g_pl[p] + o) = make_uint2(l01, l23);
    }
}

// ---------------------------------------------------------------------------
// Kernel 2: scores. CTA = one 128x128 tile of S for one batch; two phases
// (mean p={0,1}, std p={2,3}) reusing SMEM. Mask cached once as float smem,
// consumed as accumulator-layout fragments -> full register epilogue.
// ---------------------------------------------------------------------------
__global__ __launch_bounds__(256, 1)
void scores_kernel(const int* __restrict__ mask, float* __restrict__ out) {
    extern __shared__ __align__(16) char smem[];
    const int tid = threadIdx.x, wid = tid >> 5;
    const int nb0 = blockIdx.x * TILE;
    const int mb0 = blockIdx.y * TILE;
    const int b = blockIdx.z;
    const uint32_t sbase = smem_u32(smem);

    // mask -> float smem (once; reused by both phases)
    float* Ms = reinterpret_cast<float*>(smem + S_MASK);
#pragma unroll
    for (int i = 0; i < 16; i++) {
        int u = i * 256 + tid;
        int r = u >> 5, c4 = (u & 31) << 2;
        int4 mm = *reinterpret_cast<const int4*>(
            mask + ((size_t)b * L_ + mb0 + r) * L_ + nb0 + c4);
        float4 f;
        f.x = mm.x ? 1.0f : 0.0f;
        f.y = mm.y ? 1.0f : 0.0f;
        f.z = mm.z ? 1.0f : 0.0f;
        f.w = mm.w ? 1.0f : 0.0f;
        *reinterpret_cast<float4*>(Ms + r * LDC + c4) = f;
    }

    const int wm = wid & 3, wn = wid >> 2;
    const float inv_sqrt_d = 0.08838834764831845f;

    const __nv_bfloat16* sQh = reinterpret_cast<const __nv_bfloat16*>(smem + S_QH);
    const __nv_bfloat16* sQl = reinterpret_cast<const __nv_bfloat16*>(smem + S_QL);
    const __nv_bfloat16* sKh = reinterpret_cast<const __nv_bfloat16*>(smem + S_KH);
    const __nv_bfloat16* sKl = reinterpret_cast<const __nv_bfloat16*>(smem + S_KL);

    for (int phase = 0; phase < 2; phase++) {
        const size_t qoff = ((size_t)b * L_ + mb0) * D_;
        const size_t koff = ((size_t)b * L_ + nb0) * D_;
        load_tile_cp(sbase + S_QH, g_ph[2 * phase + 0] + qoff, tid);
        load_tile_cp(sbase + S_QL, g_pl[2 * phase + 0] + qoff, tid);
        load_tile_cp(sbase + S_KH, g_ph[2 * phase + 1] + koff, tid);
        load_tile_cp(sbase + S_KL, g_pl[2 * phase + 1] + koff, tid);
        cp_async_wait_all();
        __syncthreads();

        FragC acc[2][4];
#pragma unroll
        for (int i = 0; i < 2; i++)
#pragma unroll
            for (int j = 0; j < 4; j++) wmma::fill_fragment(acc[i][j], 0.0f);

#pragma unroll
        for (int pass = 0; pass < 3; pass++) {
            const __nv_bfloat16* A = (pass == 1) ? sQl : sQh;
            const __nv_bfloat16* Bm = (pass == 2) ? sKl : sKh;
#pragma unroll
            for (int k = 0; k < 8; k++) {
                FragA a[2];
                wmma::load_matrix_sync(a[0], A + (wm * 32 + 0) * LDB + k * 16, LDB);
                wmma::load_matrix_sync(a[1], A + (wm * 32 + 16) * LDB + k * 16, LDB);
#pragma unroll
                for (int j = 0; j < 4; j++) {
                    // K tile row-major [n][k] == col-major (k,n), ld = LDB
                    FragBc bfr;
                    wmma::load_matrix_sync(bfr, Bm + (wn * 64 + j * 16) * LDB + k * 16, LDB);
                    wmma::mma_sync(acc[0][j], a[0], bfr, acc[0][j]);
                    wmma::mma_sync(acc[1][j], a[1], bfr, acc[1][j]);
                }
            }
        }

        // register epilogue: scale -> tanh -> mask select -> store to global
        float* obase = out + (size_t)phase * B_ * L_ * L_ + (size_t)b * L_ * L_;
#pragma unroll
        for (int i = 0; i < 2; i++) {
#pragma unroll
            for (int j = 0; j < 4; j++) {
                int r0 = wm * 32 + i * 16, c0 = wn * 64 + j * 16;
                FragC mf;
                wmma::load_matrix_sync(mf, Ms + r0 * LDC + c0, LDC, wmma::mem_row_major);
#pragma unroll
                for (int e = 0; e < mf.num_elements; e++) {
                    float t = tanh_fast(acc[i][j].x[e] * inv_sqrt_d);
                    bool m = (mf.x[e] != 0.0f);
                    acc[i][j].x[e] = (phase == 0)
                        ? (m ? fmaf(0.5f, t, 0.5f) : 0.0f)
                        : (m ? fmaf(4.0f, t, -6.0f) : -10.0f);
                }
                wmma::store_matrix_sync(obase + (size_t)(mb0 + r0) * L_ + (nb0 + c0),
                                        acc[i][j], L_, wmma::mem_row_major);
            }
        }
        __syncthreads();  // tiles reusable for next phase
    }
}

// ---------------------------------------------------------------------------
extern "C" void kernel_launch(void* const* d_in, const int* in_sizes, int n_in,
                              void* d_out, int out_size) {
    const float* query = (const float*)d_in[0];
    const float* key   = (const float*)d_in[1];
    const int*   mask  = (const int*)d_in[2];
    const float* wqm = (const float*)d_in[3];
    const float* bqm = (const float*)d_in[4];
    const float* wkm = (const float*)d_in[5];
    const float* bkm = (const float*)d_in[6];
    const float* wqs = (const float*)d_in[7];
    const float* bqs = (const float*)d_in[8];
    const float* wks = (const float*)d_in[9];
    const float* bks = (const float*)d_in[10];
    float* out = (float*)d_out;

    cudaFuncSetAttribute(proj_kernel, cudaFuncAttributeMaxDynamicSharedMemorySize, P_SMEM);
    cudaFuncSetAttribute(scores_kernel, cudaFuncAttributeMaxDynamicSharedMemorySize, S_SMEM);

    wprep_kernel<<<dim3(64, 4), 256>>>(wqm, wkm, wqs, wks);
    proj_kernel<<<dim3((B_ * L_) / TILE, 4), 256, P_SMEM>>>(query, key, bqm, bkm, bqs, bks);
    scores_kernel<<<dim3(L_ / TILE, L_ / TILE, B_), 256, S_SMEM>>>(mask, out);
}